// round 5
// baseline (speedup 1.0000x reference)
#include <cuda_runtime.h>
#include <cstdint>
#include <math.h>

// Problem constants (fixed by the reference)
#define L_TOT 4096
#define HIDDEN 2560
#define NH 8
#define NKV 4
#define HD 256
#define SEQ 1024
#define NSEQ 4
#define QD (NH * HD)   // 2048
#define KD (NKV * HD)  // 1024

// Scratch (device globals; allocation-free per harness rules)
__device__ float g_Q[(size_t)L_TOT * QD];
__device__ float g_K[(size_t)L_TOT * KD];
__device__ float g_V[(size_t)L_TOT * KD];
__device__ float g_S[(size_t)NH * NSEQ * SEQ * SEQ];
__device__ float g_AO[(size_t)L_TOT * QD];
__device__ float g_X32[(size_t)L_TOT * HIDDEN];   // tf32-rounded inputs
__device__ float g_Wq32[(size_t)HIDDEN * QD];
__device__ float g_Wk32[(size_t)HIDDEN * KD];
__device__ float g_Wv32[(size_t)HIDDEN * KD];
__device__ float g_Wo32[(size_t)QD * HIDDEN];

// ------------------------------------------------------------------
// helpers
// ------------------------------------------------------------------
__device__ __forceinline__ void cp16(uint32_t s, const void* g) {
    asm volatile("cp.async.cg.shared.global [%0], [%1], 16;\n" ::"r"(s), "l"(g));
}
__device__ __forceinline__ void cp_commit() { asm volatile("cp.async.commit_group;\n"); }
template <int N>
__device__ __forceinline__ void cp_wait() { asm volatile("cp.async.wait_group %0;\n" ::"n"(N)); }

__device__ __forceinline__ uint32_t cvt_tf32(float x) {
    uint32_t r;
    asm("cvt.rna.tf32.f32 %0, %1;" : "=r"(r) : "f"(x));
    return r;
}
__device__ __forceinline__ float round_tf32(float x) { return __uint_as_float(cvt_tf32(x)); }

__device__ __forceinline__ void mma_tf32(float* c, const uint32_t* a, uint32_t b0, uint32_t b1) {
    asm volatile(
        "mma.sync.aligned.m16n8k8.row.col.f32.tf32.tf32.f32 "
        "{%0,%1,%2,%3}, {%4,%5,%6,%7}, {%8,%9}, {%0,%1,%2,%3};\n"
        : "+f"(c[0]), "+f"(c[1]), "+f"(c[2]), "+f"(c[3])
        : "r"(a[0]), "r"(a[1]), "r"(a[2]), "r"(a[3]), "r"(b0), "r"(b1));
}

// ------------------------------------------------------------------
// Projection GEMM: C[M,N] = A[M,K] @ B[K,N], data pre-rounded to tf32 grid.
// CTA tile 128x256, BK=16, 256 threads = 8 warps (2 x 4), warp tile 64x64.
// ------------------------------------------------------------------
#define GBM 128
#define GBN 256
#define GBK 16
#define GAS 20    // A smem stride ([m][k], 16 + 4 pad) — conflict-free
#define GBS 264   // B smem stride ([k][n], 256 + 8 pad) — conflict-free
#define GA_BYTES (GBM * GAS * 4)          // 10240
#define GB_BYTES (GBK * GBS * 4)          // 16896
#define GSMEM_TOTAL (2 * (GA_BYTES + GB_BYTES))  // 54272

template <bool ROUND>
__global__ void __launch_bounds__(256, 1) gemm_big(int K, const float* __restrict__ A, int lda,
                                                   const float* __restrict__ B, int ldb,
                                                   float* __restrict__ C, int ldc)
{
    extern __shared__ __align__(16) float smem[];
    float* As = smem;                         // [2][128*GAS]
    float* Bs = smem + 2 * GBM * GAS;         // [2][16*GBS]

    const int tid = threadIdx.x;
    const int warp = tid >> 5, lane = tid & 31;
    const int gid = lane >> 2, tig = lane & 3;
    const int wm = warp & 1, wn = warp >> 1;  // 2 x 4

    A += (size_t)blockIdx.y * GBM * lda;
    B += (size_t)blockIdx.x * GBN;
    C += (size_t)blockIdx.y * GBM * ldc + (size_t)blockIdx.x * GBN;

    float acc[4][8][4];
#pragma unroll
    for (int i = 0; i < 4; i++)
#pragma unroll
        for (int j = 0; j < 8; j++)
#pragma unroll
            for (int r = 0; r < 4; r++) acc[i][j][r] = 0.f;

    const uint32_t sA = (uint32_t)__cvta_generic_to_shared(As);
    const uint32_t sB = (uint32_t)__cvta_generic_to_shared(Bs);

    auto load_stage = [&](int buf, int k0) {
#pragma unroll
        for (int i = 0; i < 2; i++) {  // A: 512 chunks
            int ch = tid * 2 + i;
            int row = ch >> 2, c = ch & 3;
            cp16(sA + (uint32_t)(buf * GBM * GAS + row * GAS + c * 4) * 4,
                 A + (size_t)row * lda + k0 + c * 4);
        }
#pragma unroll
        for (int i = 0; i < 4; i++) {  // B: 1024 chunks
            int ch = tid * 4 + i;
            int row = ch >> 6, c = ch & 63;
            cp16(sB + (uint32_t)(buf * GBK * GBS + row * GBS + c * 4) * 4,
                 B + (size_t)(k0 + row) * ldb + c * 4);
        }
        cp_commit();
    };

    const int KT = K >> 4;
    load_stage(0, 0);

    for (int kt = 0; kt < KT; kt++) {
        cp_wait<0>();
        __syncthreads();
        const int buf = kt & 1;
        if (kt + 1 < KT) load_stage(buf ^ 1, (kt + 1) * GBK);

        const float* Ab = As + buf * GBM * GAS;
        const float* Bb = Bs + buf * GBK * GBS;
#pragma unroll
        for (int ks = 0; ks < 16; ks += 8) {
            uint32_t af[4][4];
#pragma unroll
            for (int mt = 0; mt < 4; mt++) {
                const int mrow = wm * 64 + mt * 16 + gid;
                af[mt][0] = __float_as_uint(Ab[mrow * GAS + ks + tig]);
                af[mt][1] = __float_as_uint(Ab[(mrow + 8) * GAS + ks + tig]);
                af[mt][2] = __float_as_uint(Ab[mrow * GAS + ks + tig + 4]);
                af[mt][3] = __float_as_uint(Ab[(mrow + 8) * GAS + ks + tig + 4]);
            }
#pragma unroll
            for (int nt = 0; nt < 8; nt++) {
                const int ncol = wn * 64 + nt * 8 + gid;
                const uint32_t b0 = __float_as_uint(Bb[(ks + tig) * GBS + ncol]);
                const uint32_t b1 = __float_as_uint(Bb[(ks + tig + 4) * GBS + ncol]);
#pragma unroll
                for (int mt = 0; mt < 4; mt++) mma_tf32(acc[mt][nt], af[mt], b0, b1);
            }
        }
        __syncthreads();
    }

#pragma unroll
    for (int mt = 0; mt < 4; mt++) {
        const int mrow = wm * 64 + mt * 16 + gid;
#pragma unroll
        for (int nt = 0; nt < 8; nt++) {
            const int ncol = wn * 64 + nt * 8 + 2 * tig;
            float v0 = acc[mt][nt][0], v1 = acc[mt][nt][1];
            float v2 = acc[mt][nt][2], v3 = acc[mt][nt][3];
            if (ROUND) { v0 = round_tf32(v0); v1 = round_tf32(v1); v2 = round_tf32(v2); v3 = round_tf32(v3); }
            *reinterpret_cast<float2*>(C + (size_t)mrow * ldc + ncol) = make_float2(v0, v1);
            *reinterpret_cast<float2*>(C + (size_t)(mrow + 8) * ldc + ncol) = make_float2(v2, v3);
        }
    }
}

// ------------------------------------------------------------------
// Attention GEMM core: 128x128 tile, BK=16, 8 warps (4x2), warp tile 32x64.
// Inputs pre-rounded to the tf32 grid (no cvt in mainloop).
// ------------------------------------------------------------------
#define ASTRIDE 20
#define BSTRIDE_NN 132
#define BSTRIDE_NT 20

template <bool NT, bool ROUND>
__device__ __forceinline__ void mma_gemm_body(const float* __restrict__ A, int lda,
                                              const float* __restrict__ B, int ldb,
                                              float* __restrict__ C, int ldc, int K)
{
    __shared__ float As[2][128 * ASTRIDE];
    __shared__ float Bs[2][NT ? 128 * BSTRIDE_NT : 16 * BSTRIDE_NN];

    const int tid = threadIdx.x;
    const int warp = tid >> 5, lane = tid & 31;
    const int gid = lane >> 2, tig = lane & 3;
    const int wm = warp & 3, wn = warp >> 2;

    float acc[2][8][4];
#pragma unroll
    for (int i = 0; i < 2; i++)
#pragma unroll
        for (int j = 0; j < 8; j++)
#pragma unroll
            for (int r = 0; r < 4; r++) acc[i][j][r] = 0.f;

    const uint32_t sA = (uint32_t)__cvta_generic_to_shared(&As[0][0]);
    const uint32_t sB = (uint32_t)__cvta_generic_to_shared(&Bs[0][0]);

    auto load_stage = [&](int buf, int k0) {
#pragma unroll
        for (int i = 0; i < 2; i++) {
            int chunk = tid * 2 + i;
            int row = chunk >> 2, cc = chunk & 3;
            cp16(sA + (uint32_t)(buf * 128 * ASTRIDE + row * ASTRIDE + cc * 4) * 4,
                 A + (size_t)row * lda + k0 + cc * 4);
        }
        if (NT) {
#pragma unroll
            for (int i = 0; i < 2; i++) {
                int chunk = tid * 2 + i;
                int row = chunk >> 2, cc = chunk & 3;
                cp16(sB + (uint32_t)(buf * 128 * BSTRIDE_NT + row * BSTRIDE_NT + cc * 4) * 4,
                     B + (size_t)row * ldb + k0 + cc * 4);
            }
        } else {
#pragma unroll
            for (int i = 0; i < 2; i++) {
                int chunk = tid * 2 + i;
                int row = chunk >> 5, cc = chunk & 31;
                cp16(sB + (uint32_t)(buf * 16 * BSTRIDE_NN + row * BSTRIDE_NN + cc * 4) * 4,
                     B + (size_t)(k0 + row) * ldb + cc * 4);
            }
        }
        cp_commit();
    };

    const int KT = K >> 4;
    load_stage(0, 0);

    for (int kt = 0; kt < KT; kt++) {
        cp_wait<0>();
        __syncthreads();
        const int buf = kt & 1;
        if (kt + 1 < KT) load_stage(buf ^ 1, (kt + 1) * 16);

#pragma unroll
        for (int ks = 0; ks < 16; ks += 8) {
            uint32_t af[2][4];
#pragma unroll
            for (int mt = 0; mt < 2; mt++) {
                const int mrow = wm * 32 + mt * 16 + gid;
                af[mt][0] = __float_as_uint(As[buf][mrow * ASTRIDE + ks + tig]);
                af[mt][1] = __float_as_uint(As[buf][(mrow + 8) * ASTRIDE + ks + tig]);
                af[mt][2] = __float_as_uint(As[buf][mrow * ASTRIDE + ks + tig + 4]);
                af[mt][3] = __float_as_uint(As[buf][(mrow + 8) * ASTRIDE + ks + tig + 4]);
            }
#pragma unroll
            for (int nt = 0; nt < 8; nt++) {
                const int ncol = wn * 64 + nt * 8 + gid;
                uint32_t b0, b1;
                if (NT) {
                    b0 = __float_as_uint(Bs[buf][ncol * BSTRIDE_NT + ks + tig]);
                    b1 = __float_as_uint(Bs[buf][ncol * BSTRIDE_NT + ks + tig + 4]);
                } else {
                    b0 = __float_as_uint(Bs[buf][(ks + tig) * BSTRIDE_NN + ncol]);
                    b1 = __float_as_uint(Bs[buf][(ks + tig + 4) * BSTRIDE_NN + ncol]);
                }
#pragma unroll
                for (int mt = 0; mt < 2; mt++) mma_tf32(acc[mt][nt], af[mt], b0, b1);
            }
        }
        __syncthreads();
    }

#pragma unroll
    for (int mt = 0; mt < 2; mt++) {
        const int mrow = wm * 32 + mt * 16 + gid;
#pragma unroll
        for (int nt = 0; nt < 8; nt++) {
            const int ncol = wn * 64 + nt * 8 + 2 * tig;
            float v0 = acc[mt][nt][0], v1 = acc[mt][nt][1];
            float v2 = acc[mt][nt][2], v3 = acc[mt][nt][3];
            if (ROUND) { v0 = round_tf32(v0); v1 = round_tf32(v1); v2 = round_tf32(v2); v3 = round_tf32(v3); }
            *reinterpret_cast<float2*>(C + (size_t)mrow * ldc + ncol) = make_float2(v0, v1);
            *reinterpret_cast<float2*>(C + (size_t)(mrow + 8) * ldc + ncol) = make_float2(v2, v3);
        }
    }
}

// Q @ K^T per (head, seq); skips fully-masked tiles.
__global__ void __launch_bounds__(256) scores_k()
{
    if ((int)blockIdx.x > (int)blockIdx.y) return;
    const int z = blockIdx.z;
    const int h = z >> 2, s = z & 3;
    const float* A = g_Q + (size_t)s * SEQ * QD + (size_t)h * HD + (size_t)blockIdx.y * 128 * QD;
    const float* B = g_K + (size_t)s * SEQ * KD + (size_t)(h >> 1) * HD + (size_t)blockIdx.x * 128 * KD;
    float* C = g_S + (size_t)z * SEQ * SEQ + (size_t)blockIdx.y * 128 * SEQ + (size_t)blockIdx.x * 128;
    mma_gemm_body<true, false>(A, QD, B, KD, C, SEQ, HD);
}

// P @ V per (head, seq); K truncated by causality. Rounds AO for the O-proj.
__global__ void __launch_bounds__(256) pv_k()
{
    const int z = blockIdx.z;
    const int h = z >> 2, s = z & 3;
    const float* A = g_S + (size_t)z * SEQ * SEQ + (size_t)blockIdx.y * 128 * SEQ;
    const float* B = g_V + (size_t)s * SEQ * KD + (size_t)(h >> 1) * HD + (size_t)blockIdx.x * 128;
    float* C = g_AO + (size_t)s * SEQ * QD + (size_t)h * HD + (size_t)blockIdx.y * 128 * QD +
               (size_t)blockIdx.x * 128;
    mma_gemm_body<false, true>(A, SEQ, B, KD, C, QD, (blockIdx.y + 1) * 128);
}

// tf32-round a contiguous buffer (n multiple of 1024)
__global__ void __launch_bounds__(256) round_copy(const float* __restrict__ src,
                                                  float* __restrict__ dst)
{
    size_t i = ((size_t)blockIdx.x * 256 + threadIdx.x) * 4;
    float4 v = *reinterpret_cast<const float4*>(src + i);
    v.x = round_tf32(v.x); v.y = round_tf32(v.y);
    v.z = round_tf32(v.z); v.w = round_tf32(v.w);
    *reinterpret_cast<float4*>(dst + i) = v;
}

// Per-(token, head) RMS norm + RoPE, in place; rounds output to tf32 grid.
__global__ void __launch_bounds__(256) norm_rope_kernel(float* __restrict__ X, int nHeads,
                                                        const float* __restrict__ w,
                                                        const float* __restrict__ cosb,
                                                        const float* __restrict__ sinb)
{
    const int l = blockIdx.x, h = blockIdx.y;
    float* x = X + (size_t)l * nHeads * HD + (size_t)h * HD;
    const int i = threadIdx.x;
    float v = x[i];
    __shared__ float red[256];
    __shared__ float sh[256];
    red[i] = v * v;
    __syncthreads();
    for (int s = 128; s > 0; s >>= 1) {
        if (i < s) red[i] += red[i + s];
        __syncthreads();
    }
    float r = rsqrtf(red[0] * (1.0f / HD) + 1e-6f);
    float n = v * r * (1.0f + w[i]);
    sh[i] = n;
    __syncthreads();
    float rot = (i < (HD / 2)) ? -sh[i + HD / 2] : sh[i - HD / 2];
    x[i] = round_tf32(n * cosb[(size_t)l * HD + i] + rot * sinb[(size_t)l * HD + i]);
}

// Row-wise masked softmax (scale + causal). Writes tf32-rounded P, 0 for masked.
__global__ void __launch_bounds__(256) softmax_kernel()
{
    const int z = blockIdx.y;
    const int row = blockIdx.x;
    float* S = g_S + (size_t)z * SEQ * SEQ + (size_t)row * SEQ;
    const int valid = row + 1;
    const int tid = threadIdx.x;
    float vals[4];
    float mx = -INFINITY;
#pragma unroll
    for (int j = 0; j < 4; j++) {
        int c = tid + j * 256;
        float v = (c < valid) ? S[c] * 0.0625f : -INFINITY;
        vals[j] = v;
        mx = fmaxf(mx, v);
    }
    __shared__ float red[256];
    red[tid] = mx;
    __syncthreads();
    for (int s2 = 128; s2 > 0; s2 >>= 1) {
        if (tid < s2) red[tid] = fmaxf(red[tid], red[tid + s2]);
        __syncthreads();
    }
    mx = red[0];
    __syncthreads();
    float ev[4];
    float lsum = 0.f;
#pragma unroll
    for (int j = 0; j < 4; j++) {
        int c = tid + j * 256;
        ev[j] = (c < valid) ? __expf(vals[j] - mx) : 0.f;
        lsum += ev[j];
    }
    red[tid] = lsum;
    __syncthreads();
    for (int s2 = 128; s2 > 0; s2 >>= 1) {
        if (tid < s2) red[tid] += red[tid + s2];
        __syncthreads();
    }
    float inv = 1.0f / red[0];
#pragma unroll
    for (int j = 0; j < 4; j++) {
        int c = tid + j * 256;
        S[c] = round_tf32(ev[j] * inv);
    }
}

extern "C" void kernel_launch(void* const* d_in, const int* in_sizes, int n_in,
                              void* d_out, int out_size)
{
    const float* X    = (const float*)d_in[0];
    const float* cosb = (const float*)d_in[1];
    const float* sinb = (const float*)d_in[2];
    const float* Wq   = (const float*)d_in[3];
    const float* Wk   = (const float*)d_in[4];
    const float* Wv   = (const float*)d_in[5];
    const float* Wo   = (const float*)d_in[6];
    const float* qw   = (const float*)d_in[7];
    const float* kw   = (const float*)d_in[8];
    float* out = (float*)d_out;

    float *Q, *K, *V, *AO, *X32, *Wq32, *Wk32, *Wv32, *Wo32;
    cudaGetSymbolAddress((void**)&Q, g_Q);
    cudaGetSymbolAddress((void**)&K, g_K);
    cudaGetSymbolAddress((void**)&V, g_V);
    cudaGetSymbolAddress((void**)&AO, g_AO);
    cudaGetSymbolAddress((void**)&X32, g_X32);
    cudaGetSymbolAddress((void**)&Wq32, g_Wq32);
    cudaGetSymbolAddress((void**)&Wk32, g_Wk32);
    cudaGetSymbolAddress((void**)&Wv32, g_Wv32);
    cudaGetSymbolAddress((void**)&Wo32, g_Wo32);

    cudaFuncSetAttribute(gemm_big<false>, cudaFuncAttributeMaxDynamicSharedMemorySize, GSMEM_TOTAL);
    cudaFuncSetAttribute(gemm_big<true>, cudaFuncAttributeMaxDynamicSharedMemorySize, GSMEM_TOTAL);

    // Prep: tf32-round inputs/weights (one pass each)
    round_copy<<<(L_TOT * HIDDEN) / 1024, 256>>>(X, X32);
    round_copy<<<(HIDDEN * QD) / 1024, 256>>>(Wq, Wq32);
    round_copy<<<(HIDDEN * KD) / 1024, 256>>>(Wk, Wk32);
    round_copy<<<(HIDDEN * KD) / 1024, 256>>>(Wv, Wv32);
    round_copy<<<(QD * HIDDEN) / 1024, 256>>>(Wo, Wo32);

    // QKV projections (V output rounded for the PV GEMM)
    gemm_big<false><<<dim3(QD / GBN, L_TOT / GBM), 256, GSMEM_TOTAL>>>(HIDDEN, X32, HIDDEN, Wq32, QD, Q, QD);
    gemm_big<false><<<dim3(KD / GBN, L_TOT / GBM), 256, GSMEM_TOTAL>>>(HIDDEN, X32, HIDDEN, Wk32, KD, K, KD);
    gemm_big<true><<<dim3(KD / GBN, L_TOT / GBM), 256, GSMEM_TOTAL>>>(HIDDEN, X32, HIDDEN, Wv32, KD, V, KD);

    // QK-norm + RoPE (in place, rounds to tf32 grid)
    norm_rope_kernel<<<dim3(L_TOT, NH), 256>>>(Q, NH, qw, cosb, sinb);
    norm_rope_kernel<<<dim3(L_TOT, NKV), 256>>>(K, NKV, kw, cosb, sinb);

    // Attention
    scores_k<<<dim3(SEQ / 128, SEQ / 128, NH * NSEQ), 256>>>();
    softmax_kernel<<<dim3(SEQ, NH * NSEQ), 256>>>();
    pv_k<<<dim3(HD / 128, SEQ / 128, NH * NSEQ), 256>>>();

    // Output projection
    gemm_big<false><<<dim3(HIDDEN / GBN, L_TOT / GBM), 256, GSMEM_TOTAL>>>(QD, AO, QD, Wo32, HIDDEN, out, HIDDEN);
}